// round 1
// baseline (speedup 1.0000x reference)
#include <cuda_runtime.h>
#include <math.h>
#include <stdint.h>

#define DIN      1024
#define KCHUNK   64
#define KP_CHUNK 32            // k-pairs per chunk
#define NCHUNK   (DIN / KCHUNK)
#define ROWS     128           // rows per block (== threads)
#define THREADS  128
#define XS_STRIDE 66           // floats; padding => conflict-free LDS.64

// Packed weights: [k/2][j] as float2 (w_j[k], w_j[k+1]); j: 0-2 mu, 3-5 d, 6-8 l; slot 9 pad.
__device__ float2 g_wpack[(DIN / 2) * 10];

__global__ void pack_weights_kernel(const float* __restrict__ Wmu,
                                    const float* __restrict__ Wd,
                                    const float* __restrict__ Wl) {
    int idx = blockIdx.x * blockDim.x + threadIdx.x;
    int total = (DIN / 2) * 9;
    if (idx >= total) return;
    int kp = idx / 9;
    int j  = idx % 9;
    const float* W = (j < 3) ? Wmu : (j < 6) ? Wd : Wl;
    int c = j % 3;
    int k = kp * 2;
    g_wpack[kp * 10 + j] = make_float2(W[k * 3 + c], W[(k + 1) * 3 + c]);
}

__device__ __forceinline__ float softplus_f(float x) {
    return fmaxf(x, 0.0f) + log1pf(expf(-fabsf(x)));
}

__device__ __forceinline__ void rodrigues(float a0, float a1, float a2, float R[9]) {
    float th = sqrtf(a0 * a0 + a1 * a1 + a2 * a2);
    float inv = 1.0f / th;                 // reference has no epsilon either
    float kx = a0 * inv, ky = a1 * inv, kz = a2 * inv;
    float s, c;
    sincosf(th, &s, &c);
    float ct = 1.0f - c;
    R[0] = c + kx * kx * ct;      R[1] = kx * ky * ct - kz * s; R[2] = kx * kz * ct + ky * s;
    R[3] = ky * kx * ct + kz * s; R[4] = c + ky * ky * ct;      R[5] = ky * kz * ct - kx * s;
    R[6] = kz * kx * ct - ky * s; R[7] = kz * ky * ct + kx * s; R[8] = c + kz * kz * ct;
}

__global__ __launch_bounds__(THREADS, 4)
void so3_fused_kernel(const float* __restrict__ x,
                      const float* __restrict__ eps,
                      const float* __restrict__ bmu,
                      const float* __restrict__ bd,
                      const float* __restrict__ bl,
                      float* __restrict__ out,
                      int B, int n) {
    __shared__ __align__(16) float  xs[ROWS * XS_STRIDE];
    __shared__ __align__(16) float2 ws[KP_CHUNK * 10];

    const int tid = threadIdx.x;
    const int row = blockIdx.x * ROWS + tid;   // one row per thread

    unsigned long long acc[9];
#pragma unroll
    for (int j = 0; j < 9; ++j) acc[j] = 0ull;

    unsigned xs_u = (unsigned)__cvta_generic_to_shared(xs);
    unsigned ws_u = (unsigned)__cvta_generic_to_shared(ws);
    unsigned xrow_u = xs_u + (unsigned)(tid * XS_STRIDE * 4);

    const float* xblk = x + (size_t)blockIdx.x * ROWS * DIN;

    for (int ch = 0; ch < NCHUNK; ++ch) {
        // ---- stage x tile: 128 rows x 64 cols, fully coalesced float4 reads ----
        const float* xbase = xblk + ch * KCHUNK;
#pragma unroll
        for (int i = 0; i < 16; ++i) {
            int idx = tid + i * THREADS;       // 0..2047
            int r = idx >> 4;                  // 0..127
            int c = idx & 15;                  // 0..15 (float4 index)
            float4 v = *(const float4*)(xbase + (size_t)r * DIN + c * 4);
            unsigned a = xs_u + (unsigned)((r * XS_STRIDE + c * 4) * 4);
            asm volatile("st.shared.v2.f32 [%0], {%1,%2};" :: "r"(a),     "f"(v.x), "f"(v.y));
            asm volatile("st.shared.v2.f32 [%0], {%1,%2};" :: "r"(a + 8), "f"(v.z), "f"(v.w));
        }
        // ---- stage weight chunk: 32 kp * 80B = 2560B contiguous ----
        {
            const float4* wg  = (const float4*)&g_wpack[ch * KP_CHUNK * 10];
            float4*       wsv = (float4*)ws;
#pragma unroll
            for (int i = tid; i < (KP_CHUNK * 10 * 8) / 16; i += THREADS)  // 160 float4
                wsv[i] = wg[i];
        }
        __syncthreads();

        // ---- main loop: k-pair vectorized packed-fp32 FMA ----
#pragma unroll 8
        for (int kp = 0; kp < KP_CHUNK; ++kp) {
            unsigned long long xv;
            asm("ld.shared.b64 %0, [%1];" : "=l"(xv) : "r"(xrow_u + (unsigned)(kp * 8)));
            unsigned wb = ws_u + (unsigned)(kp * 80);
            unsigned long long w0, w1, w2, w3, w4, w5, w6, w7, w8;
            asm("ld.shared.v2.u64 {%0,%1}, [%2];" : "=l"(w0), "=l"(w1) : "r"(wb));
            asm("ld.shared.v2.u64 {%0,%1}, [%2];" : "=l"(w2), "=l"(w3) : "r"(wb + 16));
            asm("ld.shared.v2.u64 {%0,%1}, [%2];" : "=l"(w4), "=l"(w5) : "r"(wb + 32));
            asm("ld.shared.v2.u64 {%0,%1}, [%2];" : "=l"(w6), "=l"(w7) : "r"(wb + 48));
            asm("ld.shared.b64 %0, [%1];"         : "=l"(w8)           : "r"(wb + 64));
            asm("fma.rn.f32x2 %0, %1, %2, %0;" : "+l"(acc[0]) : "l"(xv), "l"(w0));
            asm("fma.rn.f32x2 %0, %1, %2, %0;" : "+l"(acc[1]) : "l"(xv), "l"(w1));
            asm("fma.rn.f32x2 %0, %1, %2, %0;" : "+l"(acc[2]) : "l"(xv), "l"(w2));
            asm("fma.rn.f32x2 %0, %1, %2, %0;" : "+l"(acc[3]) : "l"(xv), "l"(w3));
            asm("fma.rn.f32x2 %0, %1, %2, %0;" : "+l"(acc[4]) : "l"(xv), "l"(w4));
            asm("fma.rn.f32x2 %0, %1, %2, %0;" : "+l"(acc[5]) : "l"(xv), "l"(w5));
            asm("fma.rn.f32x2 %0, %1, %2, %0;" : "+l"(acc[6]) : "l"(xv), "l"(w6));
            asm("fma.rn.f32x2 %0, %1, %2, %0;" : "+l"(acc[7]) : "l"(xv), "l"(w7));
            asm("fma.rn.f32x2 %0, %1, %2, %0;" : "+l"(acc[8]) : "l"(xv), "l"(w8));
        }
        __syncthreads();
    }

    // ---- horizontal reduce the f32x2 accumulators ----
    float s[9];
#pragma unroll
    for (int j = 0; j < 9; ++j) {
        float lo = __uint_as_float((unsigned)(acc[j] & 0xffffffffull));
        float hi = __uint_as_float((unsigned)(acc[j] >> 32));
        s[j] = lo + hi;
    }

    // ---- epilogue: bias, softplus, L, Rodrigues x2, 3x3 matmul ----
    float mu0 = s[0] + bmu[0], mu1 = s[1] + bmu[1], mu2 = s[2] + bmu[2];
    float sd0 = sqrtf(softplus_f(s[3] + bd[0]));
    float sd1 = sqrtf(softplus_f(s[4] + bd[1]));
    float sd2 = sqrtf(softplus_f(s[5] + bd[2]));
    float L0 = s[6] + bl[0], L1 = s[7] + bl[1], L2 = s[8] + bl[2];

    float Rm[9];
    rodrigues(mu0, mu1, mu2, Rm);

    for (int smp = 0; smp < n; ++smp) {
        const float* ep = eps + ((size_t)smp * B + row) * 3;
        float e0 = sd0 * ep[0];
        float e1 = sd1 * ep[1];
        float e2 = sd2 * ep[2];
        float v0 = e0;
        float v1 = fmaf(L0, e0, e1);
        float v2 = fmaf(L1, e0, fmaf(L2, e1, e2));

        float Rv[9];
        rodrigues(v0, v1, v2, Rv);

        float* op = out + ((size_t)smp * B + row) * 9;
#pragma unroll
        for (int i = 0; i < 3; ++i) {
#pragma unroll
            for (int j = 0; j < 3; ++j) {
                op[i * 3 + j] = Rm[i * 3 + 0] * Rv[0 * 3 + j]
                              + Rm[i * 3 + 1] * Rv[1 * 3 + j]
                              + Rm[i * 3 + 2] * Rv[2 * 3 + j];
            }
        }
    }
}

extern "C" void kernel_launch(void* const* d_in, const int* in_sizes, int n_in,
                              void* d_out, int out_size) {
    const float* x   = (const float*)d_in[0];
    const float* eps = (const float*)d_in[1];
    const float* Wmu = (const float*)d_in[2];
    const float* bmu = (const float*)d_in[3];
    const float* Wd  = (const float*)d_in[4];
    const float* bd  = (const float*)d_in[5];
    const float* Wl  = (const float*)d_in[6];
    const float* bl  = (const float*)d_in[7];

    int B = in_sizes[0] / DIN;
    int n = in_sizes[1] / (B * 3);

    int pack_total = (DIN / 2) * 9;
    pack_weights_kernel<<<(pack_total + 127) / 128, 128>>>(Wmu, Wd, Wl);
    so3_fused_kernel<<<B / ROWS, THREADS>>>(x, eps, bmu, bd, bl, (float*)d_out, B, n);
}

// round 4
// speedup vs baseline: 1.2807x; 1.2807x over previous
#include <cuda_runtime.h>
#include <math.h>
#include <stdint.h>

#define DIN      1024
#define KCHUNK   32                    // columns per chunk
#define NCHUNK   (DIN / KCHUNK)        // 32
#define GROUPS   (KCHUNK / 4)          // 8  (4 columns per group)
#define ROWS     128
#define THREADS  128
#define XWSTRIDE 36                    // words per row in smem (32 data + 4 pad)
#define XBYTES   (ROWS * XWSTRIDE * 4) // 18432
#define WOFF     XBYTES
#define WCNT     (GROUPS * 9)          // 72 float4 per chunk
#define BUFBYTES (XBYTES + WCNT * 16)  // 19584

// Packed weights: [chunk][group][j] float4 = (wj[k0],wj[k1],wj[k2],wj[k3]),
// k0 = (chunk*8+group)*4 ; j: 0-2 mu, 3-5 d, 6-8 l.
__device__ float4 g_wpack2[NCHUNK * WCNT];

__global__ void pack_weights_kernel(const float* __restrict__ Wmu,
                                    const float* __restrict__ Wd,
                                    const float* __restrict__ Wl) {
    int idx = blockIdx.x * blockDim.x + threadIdx.x;
    if (idx >= NCHUNK * WCNT) return;
    int j  = idx % 9;
    int gg = idx / 9;                  // global group index; k base = gg*4
    const float* W = (j < 3) ? Wmu : (j < 6) ? Wd : Wl;
    int c = j % 3;
    int k = gg * 4;
    g_wpack2[idx] = make_float4(W[k * 3 + c], W[(k + 1) * 3 + c],
                                W[(k + 2) * 3 + c], W[(k + 3) * 3 + c]);
}

__device__ __forceinline__ void cp16(unsigned d, const void* g) {
    asm volatile("cp.async.cg.shared.global [%0], [%1], 16;" :: "r"(d), "l"(g));
}

__device__ __forceinline__ float softplus_f(float x) {
    return fmaxf(x, 0.0f) + log1pf(expf(-fabsf(x)));
}

__device__ __forceinline__ void rodrigues(float a0, float a1, float a2, float R[9]) {
    float th = sqrtf(a0 * a0 + a1 * a1 + a2 * a2);
    float inv = 1.0f / th;             // reference has no epsilon either
    float kx = a0 * inv, ky = a1 * inv, kz = a2 * inv;
    float s, c;
    sincosf(th, &s, &c);
    float ct = 1.0f - c;
    R[0] = c + kx * kx * ct;      R[1] = kx * ky * ct - kz * s; R[2] = kx * kz * ct + ky * s;
    R[3] = ky * kx * ct + kz * s; R[4] = c + ky * ky * ct;      R[5] = ky * kz * ct - kx * s;
    R[6] = kz * kx * ct - ky * s; R[7] = kz * ky * ct + kx * s; R[8] = c + kz * kz * ct;
}

__global__ __launch_bounds__(THREADS, 4)
void so3_fused_kernel(const float* __restrict__ x,
                      const float* __restrict__ eps,
                      const float* __restrict__ bmu,
                      const float* __restrict__ bd,
                      const float* __restrict__ bl,
                      float* __restrict__ out,
                      int B, int n) {
    __shared__ __align__(16) unsigned char sbuf[2 * BUFBYTES];

    const int tid = threadIdx.x;
    const int row = blockIdx.x * ROWS + tid;   // one row per thread

    unsigned long long acc[9];
#pragma unroll
    for (int j = 0; j < 9; ++j) acc[j] = 0ull;

    unsigned sb_u = (unsigned)__cvta_generic_to_shared(sbuf);
    const float*  xblk = x + (size_t)blockIdx.x * ROWS * DIN;
    const float4* wsrc = g_wpack2;

    // ---- prefetch chunk 0 into buffer 0 ----
    {
        const float* xbase = xblk;
        unsigned bs = sb_u;
#pragma unroll
        for (int i = 0; i < 8; ++i) {
            int idx = tid + i * THREADS;       // 0..1023
            int r = idx >> 3;                  // 0..127
            int c = idx & 7;                   // 0..7 (float4 col)
            cp16(bs + (unsigned)((r * XWSTRIDE + c * 4) * 4),
                 xbase + (size_t)r * DIN + c * 4);
        }
        if (tid < WCNT) cp16(bs + WOFF + tid * 16, wsrc + tid);
        asm volatile("cp.async.commit_group;" ::: "memory");
    }

    for (int ch = 0; ch < NCHUNK; ++ch) {
        // ---- prefetch next chunk into the other buffer ----
        if (ch + 1 < NCHUNK) {
            const float* xbase = xblk + (ch + 1) * KCHUNK;
            unsigned bs = sb_u + ((ch + 1) & 1) * BUFBYTES;
#pragma unroll
            for (int i = 0; i < 8; ++i) {
                int idx = tid + i * THREADS;
                int r = idx >> 3;
                int c = idx & 7;
                cp16(bs + (unsigned)((r * XWSTRIDE + c * 4) * 4),
                     xbase + (size_t)r * DIN + c * 4);
            }
            if (tid < WCNT) cp16(bs + WOFF + tid * 16, wsrc + (ch + 1) * WCNT + tid);
            asm volatile("cp.async.commit_group;" ::: "memory");
            asm volatile("cp.async.wait_group 1;" ::: "memory");
        } else {
            asm volatile("cp.async.wait_group 0;" ::: "memory");
        }
        __syncthreads();                       // chunk ch data visible to all

        // ---- compute chunk ch ----
        unsigned bs   = sb_u + (ch & 1) * BUFBYTES;
        unsigned xrow = bs + (unsigned)(tid * XWSTRIDE * 4);
        unsigned wb   = bs + WOFF;
#pragma unroll
        for (int g = 0; g < GROUPS; ++g) {
            unsigned long long x01, x23;
            asm("ld.shared.v2.u64 {%0,%1}, [%2];"
                : "=l"(x01), "=l"(x23) : "r"(xrow + (unsigned)(g * 16)));
            unsigned wgb = wb + (unsigned)(g * 144);
#pragma unroll
            for (int j = 0; j < 9; ++j) {
                unsigned long long wa, wc;
                asm("ld.shared.v2.u64 {%0,%1}, [%2];"
                    : "=l"(wa), "=l"(wc) : "r"(wgb + (unsigned)(j * 16)));
                asm("fma.rn.f32x2 %0, %1, %2, %0;" : "+l"(acc[j]) : "l"(x01), "l"(wa));
                asm("fma.rn.f32x2 %0, %1, %2, %0;" : "+l"(acc[j]) : "l"(x23), "l"(wc));
            }
        }
        __syncthreads();                       // all reads done before buffer reuse
    }

    // ---- horizontal reduce the f32x2 accumulators ----
    float s[9];
#pragma unroll
    for (int j = 0; j < 9; ++j) {
        float lo = __uint_as_float((unsigned)(acc[j] & 0xffffffffull));
        float hi = __uint_as_float((unsigned)(acc[j] >> 32));
        s[j] = lo + hi;
    }

    // ---- epilogue ----
    float mu0 = s[0] + bmu[0], mu1 = s[1] + bmu[1], mu2 = s[2] + bmu[2];
    float sd0 = sqrtf(softplus_f(s[3] + bd[0]));
    float sd1 = sqrtf(softplus_f(s[4] + bd[1]));
    float sd2 = sqrtf(softplus_f(s[5] + bd[2]));
    float L0 = s[6] + bl[0], L1 = s[7] + bl[1], L2 = s[8] + bl[2];

    float Rm[9];
    rodrigues(mu0, mu1, mu2, Rm);

    for (int smp = 0; smp < n; ++smp) {
        const float* ep = eps + ((size_t)smp * B + row) * 3;
        float e0 = sd0 * ep[0];
        float e1 = sd1 * ep[1];
        float e2 = sd2 * ep[2];
        float v0 = e0;
        float v1 = fmaf(L0, e0, e1);
        float v2 = fmaf(L1, e0, fmaf(L2, e1, e2));

        float Rv[9];
        rodrigues(v0, v1, v2, Rv);

        float* op = out + ((size_t)smp * B + row) * 9;
#pragma unroll
        for (int i = 0; i < 3; ++i) {
#pragma unroll
            for (int j = 0; j < 3; ++j) {
                op[i * 3 + j] = Rm[i * 3 + 0] * Rv[0 * 3 + j]
                              + Rm[i * 3 + 1] * Rv[1 * 3 + j]
                              + Rm[i * 3 + 2] * Rv[2 * 3 + j];
            }
        }
    }
}

extern "C" void kernel_launch(void* const* d_in, const int* in_sizes, int n_in,
                              void* d_out, int out_size) {
    const float* x   = (const float*)d_in[0];
    const float* eps = (const float*)d_in[1];
    const float* Wmu = (const float*)d_in[2];
    const float* bmu = (const float*)d_in[3];
    const float* Wd  = (const float*)d_in[4];
    const float* bd  = (const float*)d_in[5];
    const float* Wl  = (const float*)d_in[6];
    const float* bl  = (const float*)d_in[7];

    int B = in_sizes[0] / DIN;
    int n = in_sizes[1] / (B * 3);

    int pack_total = NCHUNK * WCNT;
    pack_weights_kernel<<<(pack_total + 127) / 128, 128>>>(Wmu, Wd, Wl);
    so3_fused_kernel<<<B / ROWS, THREADS>>>(x, eps, bmu, bd, bl, (float*)d_out, B, n);
}

// round 5
// speedup vs baseline: 1.3525x; 1.0561x over previous
#include <cuda_runtime.h>
#include <math.h>
#include <stdint.h>

#define DIN      1024
#define KCHUNK   32                    // columns per chunk
#define NCHUNK   (DIN / KCHUNK)        // 32
#define GROUPS   (KCHUNK / 4)          // 8  (4 columns per group)
#define MAXROWS  128                   // smem sized for this many rows
#define THREADS  128
#define NBLOCKS  740                   // 5 * 148 -> exactly 5 blocks per SM
#define XWSTRIDE 36                    // words per row in smem (32 data + 4 pad)
#define XBYTES   (MAXROWS * XWSTRIDE * 4) // 18432
#define WOFF     XBYTES
#define WCNT     (GROUPS * 9)          // 72 float4 per chunk
#define BUFBYTES (XBYTES + WCNT * 16)  // 19584

// Packed weights: [chunk][group][j] float4 = (wj[k0],wj[k1],wj[k2],wj[k3]),
// k0 = (chunk*8+group)*4 ; j: 0-2 mu, 3-5 d, 6-8 l.
__device__ float4 g_wpack2[NCHUNK * WCNT];

__global__ void pack_weights_kernel(const float* __restrict__ Wmu,
                                    const float* __restrict__ Wd,
                                    const float* __restrict__ Wl) {
    int idx = blockIdx.x * blockDim.x + threadIdx.x;
    if (idx >= NCHUNK * WCNT) return;
    int j  = idx % 9;
    int gg = idx / 9;                  // global group index; k base = gg*4
    const float* W = (j < 3) ? Wmu : (j < 6) ? Wd : Wl;
    int c = j % 3;
    int k = gg * 4;
    g_wpack2[idx] = make_float4(W[k * 3 + c], W[(k + 1) * 3 + c],
                                W[(k + 2) * 3 + c], W[(k + 3) * 3 + c]);
}

__device__ __forceinline__ void cp16(unsigned d, const void* g) {
    asm volatile("cp.async.cg.shared.global [%0], [%1], 16;" :: "r"(d), "l"(g));
}

__device__ __forceinline__ float softplus_f(float x) {
    return fmaxf(x, 0.0f) + log1pf(expf(-fabsf(x)));
}

__device__ __forceinline__ void rodrigues(float a0, float a1, float a2, float R[9]) {
    float th = sqrtf(a0 * a0 + a1 * a1 + a2 * a2);
    float inv = 1.0f / th;             // reference has no epsilon either
    float kx = a0 * inv, ky = a1 * inv, kz = a2 * inv;
    float s, c;
    sincosf(th, &s, &c);
    float ct = 1.0f - c;
    R[0] = c + kx * kx * ct;      R[1] = kx * ky * ct - kz * s; R[2] = kx * kz * ct + ky * s;
    R[3] = ky * kx * ct + kz * s; R[4] = c + ky * ky * ct;      R[5] = ky * kz * ct - kx * s;
    R[6] = kz * kx * ct - ky * s; R[7] = kz * ky * ct + kx * s; R[8] = c + kz * kz * ct;
}

__global__ __launch_bounds__(THREADS, 5)
void so3_fused_kernel(const float* __restrict__ x,
                      const float* __restrict__ eps,
                      const float* __restrict__ bmu,
                      const float* __restrict__ bd,
                      const float* __restrict__ bl,
                      float* __restrict__ out,
                      int B, int n) {
    __shared__ __align__(16) unsigned char sbuf[2 * BUFBYTES];

    const int tid = threadIdx.x;
    const int bid = blockIdx.x;
    const int nb  = gridDim.x;

    // ---- near-uniform row partition: first `rem` blocks get r_lo+1 rows ----
    const int r_lo = B / nb;
    const int rem  = B - r_lo * nb;
    int nrows, base;
    if (bid < rem) { nrows = r_lo + 1; base = bid * (r_lo + 1); }
    else           { nrows = r_lo;     base = rem * (r_lo + 1) + (bid - rem) * r_lo; }

    unsigned long long acc[9];
#pragma unroll
    for (int j = 0; j < 9; ++j) acc[j] = 0ull;

    unsigned sb_u = (unsigned)__cvta_generic_to_shared(sbuf);
    const float*  xblk = x + (size_t)base * DIN;
    const float4* wsrc = g_wpack2;

    // whole-warp compute skip when no lane owns a row
    const bool warp_active = (tid & ~31) < nrows;

    // ---- prefetch chunk 0 into buffer 0 ----
    {
        unsigned bs = sb_u;
#pragma unroll
        for (int i = 0; i < 8; ++i) {
            int idx = tid + i * THREADS;       // 0..1023
            int r = idx >> 3;                  // 0..127
            int c = idx & 7;                   // 0..7 (float4 col)
            if (r < nrows)
                cp16(bs + (unsigned)((r * XWSTRIDE + c * 4) * 4),
                     xblk + (size_t)r * DIN + c * 4);
        }
        if (tid < WCNT) cp16(bs + WOFF + tid * 16, wsrc + tid);
        asm volatile("cp.async.commit_group;" ::: "memory");
    }

    for (int ch = 0; ch < NCHUNK; ++ch) {
        // ---- prefetch next chunk into the other buffer ----
        if (ch + 1 < NCHUNK) {
            const float* xbase = xblk + (ch + 1) * KCHUNK;
            unsigned bs = sb_u + ((ch + 1) & 1) * BUFBYTES;
#pragma unroll
            for (int i = 0; i < 8; ++i) {
                int idx = tid + i * THREADS;
                int r = idx >> 3;
                int c = idx & 7;
                if (r < nrows)
                    cp16(bs + (unsigned)((r * XWSTRIDE + c * 4) * 4),
                         xbase + (size_t)r * DIN + c * 4);
            }
            if (tid < WCNT) cp16(bs + WOFF + tid * 16, wsrc + (ch + 1) * WCNT + tid);
            asm volatile("cp.async.commit_group;" ::: "memory");
            asm volatile("cp.async.wait_group 1;" ::: "memory");
        } else {
            asm volatile("cp.async.wait_group 0;" ::: "memory");
        }
        __syncthreads();                       // chunk ch data visible to all

        // ---- compute chunk ch ----
        if (warp_active) {
            unsigned bs   = sb_u + (ch & 1) * BUFBYTES;
            unsigned xrow = bs + (unsigned)(tid * XWSTRIDE * 4);
            unsigned wb   = bs + WOFF;
#pragma unroll
            for (int g = 0; g < GROUPS; ++g) {
                unsigned long long x01, x23;
                asm("ld.shared.v2.u64 {%0,%1}, [%2];"
                    : "=l"(x01), "=l"(x23) : "r"(xrow + (unsigned)(g * 16)));
                unsigned wgb = wb + (unsigned)(g * 144);
#pragma unroll
                for (int j = 0; j < 9; ++j) {
                    unsigned long long wa, wc;
                    asm("ld.shared.v2.u64 {%0,%1}, [%2];"
                        : "=l"(wa), "=l"(wc) : "r"(wgb + (unsigned)(j * 16)));
                    asm("fma.rn.f32x2 %0, %1, %2, %0;" : "+l"(acc[j]) : "l"(x01), "l"(wa));
                    asm("fma.rn.f32x2 %0, %1, %2, %0;" : "+l"(acc[j]) : "l"(x23), "l"(wc));
                }
            }
        }
        __syncthreads();                       // all reads done before buffer reuse
    }

    if (tid >= nrows) return;
    const int row = base + tid;

    // ---- horizontal reduce the f32x2 accumulators ----
    float s[9];
#pragma unroll
    for (int j = 0; j < 9; ++j) {
        float lo = __uint_as_float((unsigned)(acc[j] & 0xffffffffull));
        float hi = __uint_as_float((unsigned)(acc[j] >> 32));
        s[j] = lo + hi;
    }

    // ---- epilogue ----
    float mu0 = s[0] + bmu[0], mu1 = s[1] + bmu[1], mu2 = s[2] + bmu[2];
    float sd0 = sqrtf(softplus_f(s[3] + bd[0]));
    float sd1 = sqrtf(softplus_f(s[4] + bd[1]));
    float sd2 = sqrtf(softplus_f(s[5] + bd[2]));
    float L0 = s[6] + bl[0], L1 = s[7] + bl[1], L2 = s[8] + bl[2];

    float Rm[9];
    rodrigues(mu0, mu1, mu2, Rm);

    for (int smp = 0; smp < n; ++smp) {
        const float* ep = eps + ((size_t)smp * B + row) * 3;
        float e0 = sd0 * ep[0];
        float e1 = sd1 * ep[1];
        float e2 = sd2 * ep[2];
        float v0 = e0;
        float v1 = fmaf(L0, e0, e1);
        float v2 = fmaf(L1, e0, fmaf(L2, e1, e2));

        float Rv[9];
        rodrigues(v0, v1, v2, Rv);

        float* op = out + ((size_t)smp * B + row) * 9;
#pragma unroll
        for (int i = 0; i < 3; ++i) {
#pragma unroll
            for (int j = 0; j < 3; ++j) {
                op[i * 3 + j] = Rm[i * 3 + 0] * Rv[0 * 3 + j]
                              + Rm[i * 3 + 1] * Rv[1 * 3 + j]
                              + Rm[i * 3 + 2] * Rv[2 * 3 + j];
            }
        }
    }
}

extern "C" void kernel_launch(void* const* d_in, const int* in_sizes, int n_in,
                              void* d_out, int out_size) {
    const float* x   = (const float*)d_in[0];
    const float* eps = (const float*)d_in[1];
    const float* Wmu = (const float*)d_in[2];
    const float* bmu = (const float*)d_in[3];
    const float* Wd  = (const float*)d_in[4];
    const float* bd  = (const float*)d_in[5];
    const float* Wl  = (const float*)d_in[6];
    const float* bl  = (const float*)d_in[7];

    int B = in_sizes[0] / DIN;
    int n = in_sizes[1] / (B * 3);

    int pack_total = NCHUNK * WCNT;
    pack_weights_kernel<<<(pack_total + 127) / 128, 128>>>(Wmu, Wd, Wl);
    so3_fused_kernel<<<NBLOCKS, THREADS>>>(x, eps, bmu, bd, bl, (float*)d_out, B, n);
}